// round 1
// baseline (speedup 1.0000x reference)
#include <cuda_runtime.h>
#include <math.h>

#define HW    96
#define NPIX  9216          // 96*96
#define NCH   21
#define KSPLIT 16
#define KSLICE 576          // NPIX / KSPLIT
#define KC    32            // k-chunk in GEMM
#define RAD   35
#define KW    71

// ---------------- device scratch (static, allocation-free) ----------------
__device__ float g_K[(size_t)NPIX * NPIX];     // 340 MB kernel matrix
__device__ float g_feat[5][NPIX];
__device__ float g_rowinv[NPIX];               // 1/(sqrt(K@1)+1e-8)
__device__ float g_U[NCH * NPIX];
__device__ float g_q[NCH * NPIX];
__device__ float g_qn[NCH * NPIX];             // q * rowinv
__device__ float g_part[KSPLIT * NCH * NPIX];  // split-K partials (12.4 MB)
__device__ float g_tmp[NCH * NPIX];
__device__ float g_qsf[NCH * NPIX];
__device__ float g_g1d[KW];                    // separable spatial weights

// ---------------- one-time setup kernels ----------------

// separable 1D gaussian weights: w[t]=exp(-(t-35)^2/72), normalized so that
// outer(w,w)/sum == (w/S) outer (w/S)
__global__ void k_g1d() {
    if (threadIdx.x == 0) {
        float w[KW];
        float s = 0.f;
        for (int t = 0; t < KW; ++t) {
            float d = (float)t - (float)RAD;
            w[t] = expf(-(d * d) / 72.0f);
            s += w[t];
        }
        float inv = 1.0f / s;
        for (int t = 0; t < KW; ++t) g_g1d[t] = w[t] * inv;
    }
}

__global__ void k_feat(const float* __restrict__ ref, const float* __restrict__ kstd) {
    int i = blockIdx.x * blockDim.x + threadIdx.x;
    if (i >= NPIX) return;
    int y = i / HW, x = i % HW;
    g_feat[0][i] = (float)y / kstd[0];
    g_feat[1][i] = (float)x / kstd[1];
    g_feat[2][i] = ref[0 * NPIX + i] / kstd[2];
    g_feat[3][i] = ref[1 * NPIX + i] / kstd[3];
    g_feat[4][i] = ref[2 * NPIX + i] / kstd[4];
}

// K tile: 32 rows x 128 cols per block, 256 threads, 16 entries/thread
__global__ void __launch_bounds__(256) k_K() {
    __shared__ float s_fr[5][32];
    __shared__ float s_fc[5][128];
    const int rowBase = blockIdx.y * 32;
    const int colBase = blockIdx.x * 128;
    const int tid = threadIdx.x;

    if (tid < 5 * 32) {
        int d = tid / 32, rr = tid % 32;
        s_fr[d][rr] = g_feat[d][rowBase + rr];
    }
    for (int idx = tid; idx < 5 * 128; idx += 256) {
        int d = idx / 128, cc = idx % 128;
        s_fc[d][cc] = g_feat[d][colBase + cc];
    }
    __syncthreads();

    const int r = tid >> 5;        // 0..7  -> rows r*4 .. r*4+3
    const int cl = tid & 31;       // 0..31 -> cols cl + 32*b

    float fr[4][5], fc[4][5];
#pragma unroll
    for (int a = 0; a < 4; ++a)
#pragma unroll
        for (int d = 0; d < 5; ++d) fr[a][d] = s_fr[d][r * 4 + a];
#pragma unroll
    for (int b = 0; b < 4; ++b)
#pragma unroll
        for (int d = 0; d < 5; ++d) fc[b][d] = s_fc[d][cl + 32 * b];

#pragma unroll
    for (int a = 0; a < 4; ++a) {
        const size_t rowOff = (size_t)(rowBase + r * 4 + a) * NPIX;
#pragma unroll
        for (int b = 0; b < 4; ++b) {
            float d2 = 0.f;
#pragma unroll
            for (int d = 0; d < 5; ++d) {
                float df = fr[a][d] - fc[b][d];
                d2 = fmaf(df, df, d2);
            }
            g_K[rowOff + colBase + cl + 32 * b] = __expf(-0.5f * d2);
        }
    }
}

// one warp per row: rowinv = 1/(sqrt(rowsum)+1e-8)
__global__ void k_rowsum() {
    int row = blockIdx.x * 8 + (threadIdx.x >> 5);
    int lane = threadIdx.x & 31;
    const float* Kr = g_K + (size_t)row * NPIX;
    float s = 0.f;
    for (int j = lane; j < NPIX; j += 32) s += Kr[j];
#pragma unroll
    for (int o = 16; o; o >>= 1) s += __shfl_xor_sync(0xffffffffu, s, o);
    if (lane == 0) g_rowinv[row] = 1.0f / (sqrtf(s) + 1e-8f);
}

__global__ void k_initq(const float* __restrict__ unary) {
    int i = blockIdx.x * blockDim.x + threadIdx.x;
    if (i >= NPIX) return;
    float ri = g_rowinv[i];
    float L[NCH];
    float m = -1e30f;
#pragma unroll
    for (int c = 0; c < NCH; ++c) {
        float u = unary[c * NPIX + i];
        u = fminf(fmaxf(u, 1e-5f), 1.0f);
        float lu = logf(u);
        g_U[c * NPIX + i] = lu;
        L[c] = lu;
        m = fmaxf(m, lu);
    }
    float se = 0.f;
#pragma unroll
    for (int c = 0; c < NCH; ++c) { L[c] = __expf(L[c] - m); se += L[c]; }
    float inv = 1.0f / se;
#pragma unroll
    for (int c = 0; c < NCH; ++c) {
        float q = L[c] * inv;
        g_q[c * NPIX + i] = q;
        g_qn[c * NPIX + i] = q * ri;
    }
}

// ---------------- per-iteration kernels ----------------

// part[z][c][j] = sum_{k in slice z} qn[c][k] * K[k][j]
// block: 256 threads, 512 cols (2 per thread), grid (18, KSPLIT)
__global__ void __launch_bounds__(256) k_gemm() {
    __shared__ float s_q[KC][24];
    const int col0 = blockIdx.x * 512;
    const int kbeg = blockIdx.y * KSLICE;
    const int tid = threadIdx.x;
    const int j0 = col0 + tid;

    float acc0[NCH], acc1[NCH];
#pragma unroll
    for (int c = 0; c < NCH; ++c) { acc0[c] = 0.f; acc1[c] = 0.f; }

    for (int kb = 0; kb < KSLICE; kb += KC) {
        __syncthreads();
#pragma unroll
        for (int idx = tid; idx < 24 * KC; idx += 256) {
            int c = idx >> 5, kk = idx & 31;
            s_q[kk][c] = (c < NCH) ? g_qn[c * NPIX + kbeg + kb + kk] : 0.f;
        }
        __syncthreads();
        const float* Kp = g_K + (size_t)(kbeg + kb) * NPIX + j0;
#pragma unroll 4
        for (int kk = 0; kk < KC; ++kk) {
            float kv0 = Kp[0];
            float kv1 = Kp[256];
            Kp += NPIX;
#pragma unroll
            for (int c = 0; c < NCH; ++c) {
                float qv = s_q[kk][c];
                acc0[c] = fmaf(qv, kv0, acc0[c]);
                acc1[c] = fmaf(qv, kv1, acc1[c]);
            }
        }
    }

    float* pp = g_part + (size_t)blockIdx.y * (NCH * NPIX);
#pragma unroll
    for (int c = 0; c < NCH; ++c) {
        pp[c * NPIX + j0] = acc0[c];
        pp[c * NPIX + j0 + 256] = acc1[c];
    }
}

__global__ void k_convY() {
    int idx = blockIdx.x * blockDim.x + threadIdx.x;
    if (idx >= NCH * NPIX) return;
    int c = idx / NPIX, p = idx % NPIX;
    int y = p / HW, x = p % HW;
    int t0 = max(-RAD, -y), t1 = min(RAD, HW - 1 - y);
    float s = 0.f;
    for (int t = t0; t <= t1; ++t)
        s = fmaf(g_g1d[t + RAD], g_q[c * NPIX + (y + t) * HW + x], s);
    g_tmp[idx] = s;
}

__global__ void k_convX() {
    int idx = blockIdx.x * blockDim.x + threadIdx.x;
    if (idx >= NCH * NPIX) return;
    int c = idx / NPIX, p = idx % NPIX;
    int y = p / HW, x = p % HW;
    int t0 = max(-RAD, -x), t1 = min(RAD, HW - 1 - x);
    float s = 0.f;
    for (int t = t0; t <= t1; ++t)
        s = fmaf(g_g1d[t + RAD], g_tmp[c * NPIX + y * HW + x + t], s);
    g_qsf[idx] = s;
}

// logits = U + 4*(rowinv * sum_z part) + 2*qsf ; softmax over channels
__global__ void k_update(float* __restrict__ out, int final_it) {
    int i = blockIdx.x * blockDim.x + threadIdx.x;
    if (i >= NPIX) return;
    float ri = g_rowinv[i];
    float* dst = final_it ? out : g_q;

    float L[NCH];
    float m = -1e30f;
#pragma unroll
    for (int c = 0; c < NCH; ++c) {
        float s = 0.f;
#pragma unroll
        for (int z = 0; z < KSPLIT; ++z) s += g_part[(z * NCH + c) * NPIX + i];
        float l = g_U[c * NPIX + i] + 4.0f * (s * ri) + 2.0f * g_qsf[c * NPIX + i];
        L[c] = l;
        m = fmaxf(m, l);
    }
    float se = 0.f;
#pragma unroll
    for (int c = 0; c < NCH; ++c) { L[c] = __expf(L[c] - m); se += L[c]; }
    float inv = 1.0f / se;
#pragma unroll
    for (int c = 0; c < NCH; ++c) {
        float q = L[c] * inv;
        dst[c * NPIX + i] = q;
        g_qn[c * NPIX + i] = q * ri;
    }
}

// ---------------- launch ----------------
extern "C" void kernel_launch(void* const* d_in, const int* in_sizes, int n_in,
                              void* d_out, int out_size) {
    const float* unary = nullptr;
    const float* ref = nullptr;
    const float* kstd = nullptr;
    for (int i = 0; i < n_in; ++i) {
        if (in_sizes[i] == NCH * NPIX) unary = (const float*)d_in[i];
        else if (in_sizes[i] == 3 * NPIX) ref = (const float*)d_in[i];
        else if (in_sizes[i] == 5) kstd = (const float*)d_in[i];
    }

    k_g1d<<<1, 32>>>();
    k_feat<<<(NPIX + 255) / 256, 256>>>(ref, kstd);
    k_K<<<dim3(NPIX / 128, NPIX / 32), 256>>>();
    k_rowsum<<<NPIX / 8, 256>>>();
    k_initq<<<(NPIX + 255) / 256, 256>>>(unary);

    for (int it = 0; it < 5; ++it) {
        k_gemm<<<dim3(NPIX / 512, KSPLIT), 256>>>();
        k_convY<<<(NCH * NPIX + 255) / 256, 256>>>();
        k_convX<<<(NCH * NPIX + 255) / 256, 256>>>();
        k_update<<<(NPIX + 255) / 256, 256>>>((float*)d_out, it == 4 ? 1 : 0);
    }
}

// round 3
// speedup vs baseline: 2.6473x; 2.6473x over previous
#include <cuda_runtime.h>
#include <cuda_fp16.h>
#include <math.h>
#include <cstdint>

#define HW      96
#define NPIX    9216
#define NCH     21
#define RAD     35
#define KW      71
#define KSPLIT  2
#define KHALF   4608          // NPIX / KSPLIT
#define CHUNK   64            // k elements per pipeline chunk
#define NCHUNK  72            // KHALF / CHUNK
#define NSTAGE  6
#define STAGE_BYTES 20480     // 16KB A + 4KB B
#define MTILES  72            // NPIX / 128

// ---------------- device scratch (static, allocation-free) ----------------
__device__ __half g_Kh[(size_t)NPIX * NPIX];     // 170 MB fp16 kernel matrix
__device__ float  g_feat[5][NPIX];
__device__ float  g_rowpart[NPIX * MTILES];
__device__ float  g_rowinv[NPIX];
__device__ float  g_U[NCH * NPIX];
__device__ float  g_q[NCH * NPIX];
__device__ __half g_qh[32 * NPIX];               // qn fp16, padded to 32 channels
__device__ float  g_part[KSPLIT * NCH * NPIX];
__device__ float  g_tmp[NCH * NPIX];
__device__ float  g_qsf[NCH * NPIX];
__device__ float  g_g1d[KW];

// ---------------- PTX helpers ----------------
__device__ __forceinline__ uint32_t s2u(const void* p) {
    uint32_t a;
    asm("{ .reg .u64 t; cvta.to.shared.u64 t, %1; cvt.u32.u64 %0, t; }" : "=r"(a) : "l"(p));
    return a;
}
#define SWZ(b) ((b) ^ (((b) >> 3) & 0x70))
#define CP16(dst, src) \
    asm volatile("cp.async.cg.shared.global [%0], [%1], 16;" :: "r"(dst), "l"(src) : "memory")
#define CP_COMMIT() asm volatile("cp.async.commit_group;" ::: "memory")
#define CP_WAIT(n)  asm volatile("cp.async.wait_group %0;" :: "n"(n) : "memory")
#define LDSM4(r0, r1, r2, r3, addr) \
    asm volatile("ldmatrix.sync.aligned.m8n8.x4.shared.b16 {%0,%1,%2,%3}, [%4];" \
                 : "=r"(r0), "=r"(r1), "=r"(r2), "=r"(r3) : "r"(addr))
#define LDSM2(r0, r1, addr) \
    asm volatile("ldmatrix.sync.aligned.m8n8.x2.shared.b16 {%0,%1}, [%2];" \
                 : "=r"(r0), "=r"(r1) : "r"(addr))
#define MMA16816(d, a0, a1, a2, a3, b0, b1) \
    asm volatile("mma.sync.aligned.m16n8k16.row.col.f32.f16.f16.f32 " \
                 "{%0,%1,%2,%3}, {%4,%5,%6,%7}, {%8,%9}, {%0,%1,%2,%3};" \
                 : "+f"((d)[0]), "+f"((d)[1]), "+f"((d)[2]), "+f"((d)[3]) \
                 : "r"(a0), "r"(a1), "r"(a2), "r"(a3), "r"(b0), "r"(b1))

// ---------------- one-time setup kernels ----------------
__global__ void k_g1d() {
    if (threadIdx.x == 0) {
        float w[KW]; float s = 0.f;
        for (int t = 0; t < KW; ++t) {
            float d = (float)t - (float)RAD;
            w[t] = expf(-(d * d) / 72.0f); s += w[t];
        }
        float inv = 1.0f / s;
        for (int t = 0; t < KW; ++t) g_g1d[t] = w[t] * inv;
    }
}

__global__ void k_feat(const float* __restrict__ ref, const float* __restrict__ kstd) {
    int i = blockIdx.x * blockDim.x + threadIdx.x;
    if (i >= NPIX) return;
    int y = i / HW, x = i % HW;
    g_feat[0][i] = (float)y / kstd[0];
    g_feat[1][i] = (float)x / kstd[1];
    g_feat[2][i] = ref[0 * NPIX + i] / kstd[2];
    g_feat[3][i] = ref[1 * NPIX + i] / kstd[3];
    g_feat[4][i] = ref[2 * NPIX + i] / kstd[4];
}

// K tile: 32 rows x 128 cols, fp16 output + deterministic fp32 row partials
__global__ void __launch_bounds__(256) k_K() {
    __shared__ float s_fr[5][32];
    __shared__ float s_fc[5][128];
    const int rowBase = blockIdx.y * 32;
    const int colBase = blockIdx.x * 128;
    const int tid = threadIdx.x;

    if (tid < 5 * 32) { int d = tid / 32, rr = tid % 32; s_fr[d][rr] = g_feat[d][rowBase + rr]; }
    for (int idx = tid; idx < 5 * 128; idx += 256) {
        int d = idx / 128, cc = idx % 128;
        s_fc[d][cc] = g_feat[d][colBase + cc];
    }
    __syncthreads();

    const int r = tid >> 5;
    const int cl = tid & 31;

    float fr[4][5], fc[4][5];
#pragma unroll
    for (int a = 0; a < 4; ++a)
#pragma unroll
        for (int d = 0; d < 5; ++d) fr[a][d] = s_fr[d][r * 4 + a];
#pragma unroll
    for (int b = 0; b < 4; ++b)
#pragma unroll
        for (int d = 0; d < 5; ++d) fc[b][d] = s_fc[d][cl + 32 * b];

#pragma unroll
    for (int a = 0; a < 4; ++a) {
        const int row = rowBase + r * 4 + a;
        const size_t rowOff = (size_t)row * NPIX;
        float rs = 0.f;
#pragma unroll
        for (int b = 0; b < 4; ++b) {
            float d2 = 0.f;
#pragma unroll
            for (int d = 0; d < 5; ++d) {
                float df = fr[a][d] - fc[b][d];
                d2 = fmaf(df, df, d2);
            }
            float v = __expf(-0.5f * d2);
            rs += v;
            g_Kh[rowOff + colBase + cl + 32 * b] = __float2half_rn(v);
        }
#pragma unroll
        for (int o = 16; o; o >>= 1) rs += __shfl_xor_sync(0xffffffffu, rs, o);
        if (cl == 0) g_rowpart[row * MTILES + blockIdx.x] = rs;
    }
}

__global__ void k_rowsumF() {
    int row = blockIdx.x * blockDim.x + threadIdx.x;
    if (row >= NPIX) return;
    float s = 0.f;
    const float* p = g_rowpart + row * MTILES;
#pragma unroll
    for (int b = 0; b < MTILES; ++b) s += p[b];
    g_rowinv[row] = 1.0f / (sqrtf(s) + 1e-8f);
}

__global__ void k_initq(const float* __restrict__ unary) {
    int i = blockIdx.x * blockDim.x + threadIdx.x;
    if (i >= NPIX) return;
    float ri = g_rowinv[i];
    float L[NCH];
    float m = -1e30f;
#pragma unroll
    for (int c = 0; c < NCH; ++c) {
        float u = unary[c * NPIX + i];
        u = fminf(fmaxf(u, 1e-5f), 1.0f);
        float lu = logf(u);
        g_U[c * NPIX + i] = lu;
        L[c] = lu;
        m = fmaxf(m, lu);
    }
    float se = 0.f;
#pragma unroll
    for (int c = 0; c < NCH; ++c) { L[c] = __expf(L[c] - m); se += L[c]; }
    float inv = 1.0f / se;
#pragma unroll
    for (int c = 0; c < NCH; ++c) {
        float q = L[c] * inv;
        g_q[c * NPIX + i] = q;
        g_qh[c * NPIX + i] = __float2half_rn(q * ri);
    }
#pragma unroll
    for (int c = NCH; c < 32; ++c) g_qh[c * NPIX + i] = __float2half_rn(0.f);
}

// ---------------- HMMA split-K GEMM: part[z] = K[:, zslice] @ qn[zslice, :]^T ----------------
// 256 threads = 8 warps; warp w owns rows [m0+16w, m0+16w+16); N = 24 effective channels
__global__ void __launch_bounds__(256, 1) k_gemm_mma() {
    extern __shared__ char dynRaw[];
    const uint32_t dynb = (s2u(dynRaw) + 1023u) & ~1023u;
    const int tid = threadIdx.x, w = tid >> 5, lid = tid & 31;
    const int m0 = blockIdx.x * 128;
    const int zbase = blockIdx.y * KHALF;

    const __half* Abase = g_Kh + (size_t)m0 * NPIX + zbase;
    const __half* Bbase = g_qh + zbase;

    auto load_chunk = [&](int ci) {
        const uint32_t bufA = dynb + (uint32_t)(ci % NSTAGE) * STAGE_BYTES;
        const uint32_t bufB = bufA + 16384;
        const int koff = ci * CHUNK;
#pragma unroll
        for (int u = tid; u < 1280; u += 256) {
            uint32_t dst; const void* src;
            if (u < 1024) {
                int r = u >> 3, t = u & 7;
                src = Abase + (size_t)r * NPIX + koff + t * 8;
                dst = bufA + SWZ((uint32_t)(r * 128 + t * 16));
            } else {
                int v = u - 1024;
                int c = v >> 3, t = v & 7;
                src = Bbase + (size_t)c * NPIX + koff + t * 8;
                dst = bufB + SWZ((uint32_t)(c * 128 + t * 16));
            }
            CP16(dst, src);
        }
        CP_COMMIT();
    };

    float acc[3][4];
#pragma unroll
    for (int g = 0; g < 3; ++g)
#pragma unroll
        for (int k = 0; k < 4; ++k) acc[g][k] = 0.f;

    for (int i = 0; i < NSTAGE - 1; ++i) load_chunk(i);

    // per-warp static address components
    const uint32_t aRowOff = (uint32_t)((w * 16 + (lid & 15)) * 128) + ((lid >> 4) << 4);
    const uint32_t bRowOff01 = (uint32_t)(((lid & 7) + ((lid >> 4) << 3)) * 128) + (((lid >> 3) & 1) << 4);
    const uint32_t bRowOff2 = (uint32_t)((16 + (lid & 7)) * 128) + (((lid >> 3) & 1) << 4);

    for (int i = 0; i < NCHUNK; ++i) {
        if (i + NSTAGE - 1 < NCHUNK) CP_WAIT(NSTAGE - 2); else CP_WAIT(0);
        __syncthreads();

        const uint32_t bufA = dynb + (uint32_t)(i % NSTAGE) * STAGE_BYTES;
        const uint32_t bufB = bufA + 16384;
#pragma unroll
        for (int ks = 0; ks < 4; ++ks) {
            const uint32_t kb = (uint32_t)ks * 32;
            uint32_t a0, a1, a2, a3;
            LDSM4(a0, a1, a2, a3, bufA + SWZ(aRowOff + kb));
            uint32_t b00, b01, b10, b11, b20, b21;
            LDSM4(b00, b01, b10, b11, bufB + SWZ(bRowOff01 + kb));
            LDSM2(b20, b21, bufB + SWZ(bRowOff2 + kb));
            MMA16816(acc[0], a0, a1, a2, a3, b00, b01);
            MMA16816(acc[1], a0, a1, a2, a3, b10, b11);
            MMA16816(acc[2], a0, a1, a2, a3, b20, b21);
        }
        __syncthreads();
        if (i + NSTAGE - 1 < NCHUNK) load_chunk(i + NSTAGE - 1);
    }

    // epilogue: c fragment mapping -> g_part
    const int row0 = m0 + w * 16 + (lid >> 2);
    const int c0 = (lid & 3) * 2;
    float* pp = g_part + (size_t)blockIdx.y * (NCH * NPIX);
#pragma unroll
    for (int g = 0; g < 3; ++g) {
#pragma unroll
        for (int k = 0; k < 4; ++k) {
            int c = g * 8 + c0 + (k & 1);
            int row = row0 + ((k >> 1) << 3);
            if (c < NCH) pp[c * NPIX + row] = acc[g][k];
        }
    }
}

// ---------------- spatial filter + update ----------------
__global__ void k_convY() {
    int idx = blockIdx.x * blockDim.x + threadIdx.x;
    if (idx >= NCH * NPIX) return;
    int c = idx / NPIX, p = idx % NPIX;
    int y = p / HW, x = p % HW;
    int t0 = max(-RAD, -y), t1 = min(RAD, HW - 1 - y);
    float s = 0.f;
    for (int t = t0; t <= t1; ++t)
        s = fmaf(g_g1d[t + RAD], g_q[c * NPIX + (y + t) * HW + x], s);
    g_tmp[idx] = s;
}

__global__ void k_convX() {
    int idx = blockIdx.x * blockDim.x + threadIdx.x;
    if (idx >= NCH * NPIX) return;
    int c = idx / NPIX, p = idx % NPIX;
    int y = p / HW, x = p % HW;
    int t0 = max(-RAD, -x), t1 = min(RAD, HW - 1 - x);
    float s = 0.f;
    for (int t = t0; t <= t1; ++t)
        s = fmaf(g_g1d[t + RAD], g_tmp[c * NPIX + y * HW + x + t], s);
    g_qsf[idx] = s;
}

__global__ void k_update(float* __restrict__ out, int final_it) {
    int i = blockIdx.x * blockDim.x + threadIdx.x;
    if (i >= NPIX) return;
    float ri = g_rowinv[i];
    float* dst = final_it ? out : g_q;

    float L[NCH];
    float m = -1e30f;
#pragma unroll
    for (int c = 0; c < NCH; ++c) {
        float s = g_part[c * NPIX + i] + g_part[(NCH + c) * NPIX + i];
        float l = g_U[c * NPIX + i] + 4.0f * (s * ri) + 2.0f * g_qsf[c * NPIX + i];
        L[c] = l;
        m = fmaxf(m, l);
    }
    float se = 0.f;
#pragma unroll
    for (int c = 0; c < NCH; ++c) { L[c] = __expf(L[c] - m); se += L[c]; }
    float inv = 1.0f / se;
#pragma unroll
    for (int c = 0; c < NCH; ++c) {
        float q = L[c] * inv;
        dst[c * NPIX + i] = q;
        g_qh[c * NPIX + i] = __float2half_rn(q * ri);
    }
}

// ---------------- launch ----------------
extern "C" void kernel_launch(void* const* d_in, const int* in_sizes, int n_in,
                              void* d_out, int out_size) {
    const float* unary = nullptr;
    const float* ref = nullptr;
    const float* kstd = nullptr;
    for (int i = 0; i < n_in; ++i) {
        if (in_sizes[i] == NCH * NPIX) unary = (const float*)d_in[i];
        else if (in_sizes[i] == 3 * NPIX) ref = (const float*)d_in[i];
        else if (in_sizes[i] == 5) kstd = (const float*)d_in[i];
    }

    cudaFuncSetAttribute(k_gemm_mma, cudaFuncAttributeMaxDynamicSharedMemorySize,
                         NSTAGE * STAGE_BYTES + 1024);

    k_g1d<<<1, 32>>>();
    k_feat<<<(NPIX + 255) / 256, 256>>>(ref, kstd);
    k_K<<<dim3(NPIX / 128, NPIX / 32), 256>>>();
    k_rowsumF<<<NPIX / 256, 256>>>();
    k_initq<<<(NPIX + 255) / 256, 256>>>(unary);

    for (int it = 0; it < 5; ++it) {
        k_gemm_mma<<<dim3(MTILES, KSPLIT), 256, NSTAGE * STAGE_BYTES + 1024>>>();
        k_convY<<<(NCH * NPIX + 255) / 256, 256>>>();
        k_convX<<<(NCH * NPIX + 255) / 256, 256>>>();
        k_update<<<(NPIX + 255) / 256, 256>>>((float*)d_out, it == 4 ? 1 : 0);
    }
}